// round 4
// baseline (speedup 1.0000x reference)
#include <cuda_runtime.h>
#include <cstdint>
#include <cstddef>

#define NB 4
#define P  2048
#define D  64
#define ITERS   50
#define NBLOCKS 512
#define NTHREADS 256
#define RCHUNKS 32
#define CHUNK_ROWS 64
// 10 * log2(e)
#define K2E 14.4269504089f
// log2(1/2048 + 1e-8)
#define LOG_MU2 (-10.99997045f)
#define LOG_NU2 (-10.99997045f)
#define NEG_BIG (-3.0e38f)

__device__ __forceinline__ float ex2f(float x) {
    float r; asm("ex2.approx.f32 %0, %1;" : "=f"(r) : "f"(x)); return r;
}
__device__ __forceinline__ float lg2f(float x) {
    float r; asm("lg2.approx.f32 %0, %1;" : "=f"(r) : "f"(x)); return r;
}

// ---------------- static device scratch -----------------------------------
__device__ float g_us2[NB * P];
__device__ float g_vs2[NB * P];
__device__ float g_xx[NB * P];
__device__ float g_yy[NB * P];
__device__ float g_pm2[NB * RCHUNKS * P];
__device__ float g_ps2[NB * RCHUNKS * P];
__device__ float g_cp[NB * 1024];
__device__ unsigned g_ticket[NB * 4];
__device__ unsigned g_barcnt;
__device__ volatile unsigned g_bargen;

// ---------------- init -------------------------------------------------------
__global__ void init_kernel() {
    int t = blockIdx.x * 256 + threadIdx.x;
    if (t < NB * P) g_vs2[t] = 0.0f;
    if (t < NB * 4) g_ticket[t] = 0u;
    if (t == 0) { g_barcnt = 0u; g_bargen = 0u; }
}

// ---------------- squared norms ----------------------------------------------
__global__ __launch_bounds__(256) void norms_kernel(const float* __restrict__ x,
                                                    const float* __restrict__ y) {
    const int r = blockIdx.x * 256 + threadIdx.x;
    const float4* xr = (const float4*)(x + (size_t)r * D);
    const float4* yr = (const float4*)(y + (size_t)r * D);
    float ax = 0.0f, ay = 0.0f;
#pragma unroll
    for (int t = 0; t < D / 4; t++) {
        float4 a = xr[t], b = yr[t];
        ax = fmaf(a.x, a.x, ax); ax = fmaf(a.y, a.y, ax);
        ax = fmaf(a.z, a.z, ax); ax = fmaf(a.w, a.w, ax);
        ay = fmaf(b.x, b.x, ay); ay = fmaf(b.y, b.y, ay);
        ay = fmaf(b.z, b.z, ay); ay = fmaf(b.w, b.w, ay);
    }
    g_xx[r] = ax;
    g_yy[r] = ay;
}

// ---------------- C = xx_i + yy_j - 2*x.y ---------------------------------------
__global__ __launch_bounds__(256) void c_kernel(const float* __restrict__ x,
                                                const float* __restrict__ y,
                                                float* __restrict__ C) {
    __shared__ float Xs[64][68];
    __shared__ float Ys[64][68];
    const int tx = threadIdx.x, ty = threadIdx.y;
    const int tid = ty * 16 + tx;
    const int n  = blockIdx.z;
    const int i0 = blockIdx.y * 64;
    const int j0 = blockIdx.x * 64;

    {
        const int r  = tid >> 2;
        const int c4 = tid & 3;
        const float* xg = x + ((size_t)n * P + i0 + r) * D;
        const float* yg = y + ((size_t)n * P + j0 + r) * D;
#pragma unroll
        for (int q = 0; q < 4; q++) {
            int col = c4 * 16 + q * 4;
            *(float4*)&Xs[r][col] = *(const float4*)(xg + col);
            *(float4*)&Ys[r][col] = *(const float4*)(yg + col);
        }
    }
    __syncthreads();

    float acc[4][4];
#pragma unroll
    for (int a = 0; a < 4; a++)
#pragma unroll
        for (int b = 0; b < 4; b++) acc[a][b] = 0.0f;

#pragma unroll
    for (int k = 0; k < D; k += 4) {
        float4 xa[4], yb[4];
#pragma unroll
        for (int a = 0; a < 4; a++) xa[a] = *(float4*)&Xs[ty * 4 + a][k];
#pragma unroll
        for (int b = 0; b < 4; b++) yb[b] = *(float4*)&Ys[tx * 4 + b][k];
#pragma unroll
        for (int a = 0; a < 4; a++)
#pragma unroll
            for (int b = 0; b < 4; b++) {
                acc[a][b] = fmaf(xa[a].x, yb[b].x, acc[a][b]);
                acc[a][b] = fmaf(xa[a].y, yb[b].y, acc[a][b]);
                acc[a][b] = fmaf(xa[a].z, yb[b].z, acc[a][b]);
                acc[a][b] = fmaf(xa[a].w, yb[b].w, acc[a][b]);
            }
    }

    float yyv[4];
#pragma unroll
    for (int b = 0; b < 4; b++) yyv[b] = g_yy[(n << 11) + j0 + tx * 4 + b];

    float* Cb = C + (size_t)n * P * P;
#pragma unroll
    for (int a = 0; a < 4; a++) {
        float xxv = g_xx[(n << 11) + i0 + ty * 4 + a];
        float4 o;
        o.x = fmaf(-2.0f, acc[a][0], xxv + yyv[0]);
        o.y = fmaf(-2.0f, acc[a][1], xxv + yyv[1]);
        o.z = fmaf(-2.0f, acc[a][2], xxv + yyv[2]);
        o.w = fmaf(-2.0f, acc[a][3], xxv + yyv[3]);
        *(float4*)&Cb[(size_t)(i0 + ty * 4 + a) * P + j0 + tx * 4] = o;
    }
}

// ---------------- LSE helpers ---------------------------------------------------
__device__ __forceinline__ void lse_group(float4 c, float vx, float vy, float vz, float vw,
                                          float& m, float& s) {
    float b0 = fmaf(c.x, -K2E, vx);
    float b1 = fmaf(c.y, -K2E, vy);
    float b2 = fmaf(c.z, -K2E, vz);
    float b3 = fmaf(c.w, -K2E, vw);
    float cm = fmaxf(fmaxf(b0, b1), fmaxf(b2, b3));
    float mn = fmaxf(m, cm);
    s = fmaf(s, ex2f(m - mn),
             ex2f(b0 - mn) + ex2f(b1 - mn) + ex2f(b2 - mn) + ex2f(b3 - mn));
    m = mn;
}

// ---------------- software grid barrier -----------------------------------------
__device__ __forceinline__ void gridbar() {
    __syncthreads();
    if (threadIdx.x == 0) {
        __threadfence();
        unsigned gen = g_bargen;
        if (atomicAdd(&g_barcnt, 1u) == NBLOCKS - 1) {
            g_barcnt = 0u;
            __threadfence();
            g_bargen = gen + 1u;
        } else {
            while (g_bargen == gen) __nanosleep(20);
        }
        __threadfence();
    }
    __syncthreads();
}

// ---------------- persistent Sinkhorn loop ---------------------------------------
__global__ __launch_bounds__(NTHREADS, 4) void sinkhorn_persistent(const float* __restrict__ C) {
    __shared__ float sbuf[P];          // row phase: vs[2048]; col phase: us[64]
    __shared__ unsigned lastv;

    const int b    = blockIdx.x;
    const int tid  = threadIdx.x;
    const int lane = tid & 31;
    const int warp = tid >> 5;
    const int n    = b >> 7;           // batch (same for row & col mapping)
    const int chunk = (b >> 2) & 31;   // col-phase row chunk
    const int jb    = b & 3;           // col-phase column block (512 cols)

    const int rowA = (b << 4) + (warp << 1);
    const int rowB = rowA + 1;
    const float4* Arow = (const float4*)(C + (size_t)rowA * P);
    const float4* Brow = (const float4*)(C + (size_t)rowB * P);
    const float4* vsrc = (const float4*)(g_vs2 + (n << 11));

    for (int it = 0; it < ITERS; it++) {
        // ---------------- row phase: u update --------------------------------
        {
            float4* vdst = (float4*)sbuf;
#pragma unroll
            for (int t = tid; t < P / 4; t += NTHREADS) vdst[t] = vsrc[t];
        }
        __syncthreads();

        float mA0 = NEG_BIG, sA0 = 0.0f, mA1 = NEG_BIG, sA1 = 0.0f;
        float mB0 = NEG_BIG, sB0 = 0.0f, mB1 = NEG_BIG, sB1 = 0.0f;
        const float4* V4 = (const float4*)sbuf;
#pragma unroll
        for (int itv = 0; itv < 8; itv++) {
            const int t0 = lane + itv * 64;
            const int t1 = t0 + 32;
            float4 a0 = Arow[t0];
            float4 b0 = Brow[t0];
            float4 a1 = Arow[t1];
            float4 b1 = Brow[t1];
            float4 v0 = V4[t0];
            float4 v1 = V4[t1];
            lse_group(a0, v0.x, v0.y, v0.z, v0.w, mA0, sA0);
            lse_group(b0, v0.x, v0.y, v0.z, v0.w, mB0, sB0);
            lse_group(a1, v1.x, v1.y, v1.z, v1.w, mA1, sA1);
            lse_group(b1, v1.x, v1.y, v1.z, v1.w, mB1, sB1);
        }
        float mA = fmaxf(mA0, mA1);
        float sA = sA0 * ex2f(mA0 - mA) + sA1 * ex2f(mA1 - mA);
        float mB = fmaxf(mB0, mB1);
        float sB = sB0 * ex2f(mB0 - mB) + sB1 * ex2f(mB1 - mB);
#pragma unroll
        for (int o = 16; o; o >>= 1) {
            float mo = __shfl_xor_sync(0xffffffffu, mA, o);
            float so = __shfl_xor_sync(0xffffffffu, sA, o);
            float mn = fmaxf(mA, mo);
            sA = sA * ex2f(mA - mn) + so * ex2f(mo - mn);
            mA = mn;
            mo = __shfl_xor_sync(0xffffffffu, mB, o);
            so = __shfl_xor_sync(0xffffffffu, sB, o);
            mn = fmaxf(mB, mo);
            sB = sB * ex2f(mB - mn) + so * ex2f(mo - mn);
            mB = mn;
        }
        if (lane == 0) {
            g_us2[rowA] = LOG_MU2 - (mA + lg2f(sA));
            g_us2[rowB] = LOG_MU2 - (mB + lg2f(sB));
        }

        gridbar();

        // ---------------- col phase: v update --------------------------------
        const int i0 = chunk << 6;
        if (tid < CHUNK_ROWS) sbuf[tid] = g_us2[(n << 11) + i0 + tid];
        __syncthreads();

        const int j0 = (jb << 9) + (tid << 1);
        const float2* Cc = (const float2*)(C + (size_t)n * P * P + (size_t)i0 * P) + (j0 >> 1);

        float m0a = NEG_BIG, s0a = 0.0f, m0b = NEG_BIG, s0b = 0.0f;  // col j0
        float m1a = NEG_BIG, s1a = 0.0f, m1b = NEG_BIG, s1b = 0.0f;  // col j0+1
#pragma unroll
        for (int i = 0; i < CHUNK_ROWS; i += 8) {
            float2 r0 = Cc[(size_t)(i + 0) * (P / 2)];
            float2 r1 = Cc[(size_t)(i + 1) * (P / 2)];
            float2 r2 = Cc[(size_t)(i + 2) * (P / 2)];
            float2 r3 = Cc[(size_t)(i + 3) * (P / 2)];
            float2 r4 = Cc[(size_t)(i + 4) * (P / 2)];
            float2 r5 = Cc[(size_t)(i + 5) * (P / 2)];
            float2 r6 = Cc[(size_t)(i + 6) * (P / 2)];
            float2 r7 = Cc[(size_t)(i + 7) * (P / 2)];
            float4 lo0 = {r0.x, r1.x, r2.x, r3.x};
            float4 hi0 = {r4.x, r5.x, r6.x, r7.x};
            float4 lo1 = {r0.y, r1.y, r2.y, r3.y};
            float4 hi1 = {r4.y, r5.y, r6.y, r7.y};
            lse_group(lo0, sbuf[i], sbuf[i + 1], sbuf[i + 2], sbuf[i + 3], m0a, s0a);
            lse_group(lo1, sbuf[i], sbuf[i + 1], sbuf[i + 2], sbuf[i + 3], m1a, s1a);
            lse_group(hi0, sbuf[i + 4], sbuf[i + 5], sbuf[i + 6], sbuf[i + 7], m0b, s0b);
            lse_group(hi1, sbuf[i + 4], sbuf[i + 5], sbuf[i + 6], sbuf[i + 7], m1b, s1b);
        }
        float m0 = fmaxf(m0a, m0b);
        float s0 = s0a * ex2f(m0a - m0) + s0b * ex2f(m0b - m0);
        float m1 = fmaxf(m1a, m1b);
        float s1 = s1a * ex2f(m1a - m1) + s1b * ex2f(m1b - m1);

        const size_t po = ((size_t)n * RCHUNKS + chunk) * P + j0;
        g_pm2[po] = m0; g_pm2[po + 1] = m1;
        g_ps2[po] = s0; g_ps2[po + 1] = s1;

        __threadfence();
        if (tid == 0) lastv = atomicAdd(&g_ticket[n * 4 + jb], 1u);
        __syncthreads();
        if (lastv == RCHUNKS - 1) {
            __threadfence();
#pragma unroll
            for (int cc = 0; cc < 2; cc++) {
                const int j = j0 + cc;
                float mm = NEG_BIG;
#pragma unroll
                for (int c = 0; c < RCHUNKS; c++)
                    mm = fmaxf(mm, __ldcg(&g_pm2[((size_t)n * RCHUNKS + c) * P + j]));
                float ss = 0.0f;
#pragma unroll
                for (int c = 0; c < RCHUNKS; c++) {
                    size_t idx = ((size_t)n * RCHUNKS + c) * P + j;
                    ss += __ldcg(&g_ps2[idx]) * ex2f(__ldcg(&g_pm2[idx]) - mm);
                }
                g_vs2[(n << 11) + j] = LOG_NU2 - (mm + lg2f(ss));
            }
            if (tid == 0) g_ticket[n * 4 + jb] = 0u;
        }

        gridbar();
    }
}

// ---------------- pi + cost partials ----------------------------------------------
__global__ __launch_bounds__(256) void pi_cost(const float* __restrict__ C,
                                               float* __restrict__ pi) {
    __shared__ float red[256];
    const int b = blockIdx.x;
    const int n = b >> 10;
    const float4* C4 = (const float4*)C;
    float4* P4 = (float4*)pi;
    const float4* V4 = (const float4*)(g_vs2 + (n << 11));
    const size_t base = (size_t)b * 1024;

    float acc = 0.0f;
#pragma unroll
    for (int p = 0; p < 4; p++) {
        size_t f4 = base + (size_t)p * 256 + threadIdx.x;
        float4 c = C4[f4];
        int ig = (int)(f4 >> 9);
        float u = g_us2[ig];
        float4 vv = V4[f4 & (P / 4 - 1)];
        float4 pv;
        pv.x = ex2f(fmaf(c.x, -K2E, u + vv.x));
        pv.y = ex2f(fmaf(c.y, -K2E, u + vv.y));
        pv.z = ex2f(fmaf(c.z, -K2E, u + vv.z));
        pv.w = ex2f(fmaf(c.w, -K2E, u + vv.w));
        P4[f4] = pv;
        acc += pv.x * c.x + pv.y * c.y + pv.z * c.z + pv.w * c.w;
    }
    red[threadIdx.x] = acc;
    __syncthreads();
#pragma unroll
    for (int o = 128; o; o >>= 1) {
        if (threadIdx.x < o) red[threadIdx.x] += red[threadIdx.x + o];
        __syncthreads();
    }
    if (threadIdx.x == 0) g_cp[b] = red[0];
}

__global__ __launch_bounds__(256) void cost_combine(float* __restrict__ cost) {
    __shared__ float red[256];
    const int n = blockIdx.x;
    float a = 0.0f;
#pragma unroll
    for (int q = 0; q < 4; q++)
        a += g_cp[n * 1024 + q * 256 + threadIdx.x];
    red[threadIdx.x] = a;
    __syncthreads();
#pragma unroll
    for (int o = 128; o; o >>= 1) {
        if (threadIdx.x < o) red[threadIdx.x] += red[threadIdx.x + o];
        __syncthreads();
    }
    if (threadIdx.x == 0) cost[n] = red[0];
}

// ---------------- launch --------------------------------------------------------------
extern "C" void kernel_launch(void* const* d_in, const int* in_sizes, int n_in,
                              void* d_out, int out_size) {
    const float* x = (const float*)d_in[0];
    const float* y = (const float*)d_in[1];
    float* out  = (float*)d_out;
    float* cost = out;
    float* pi   = out + NB;
    float* C    = out + NB + (size_t)NB * P * P;

    init_kernel<<<32, 256>>>();
    norms_kernel<<<NB * P / 256, 256>>>(x, y);
    c_kernel<<<dim3(P / 64, P / 64, NB), dim3(16, 16)>>>(x, y, C);
    sinkhorn_persistent<<<NBLOCKS, NTHREADS>>>(C);
    pi_cost<<<NB * 1024, 256>>>(C, pi);
    cost_combine<<<NB, 256>>>(cost);
}

// round 5
// speedup vs baseline: 1.1154x; 1.1154x over previous
#include <cuda_runtime.h>
#include <cstdint>
#include <cstddef>

#define NB 4
#define P  2048
#define D  64
#define ITERS   50
#define RCHUNKS 32
#define CHUNK_ROWS 64            // P / RCHUNKS
#define JBLKS   4                // P / 512 (512 cols per col-block)
// 10 * log2(e)
#define K2E 14.4269504089f
// log2(1/2048 + 1e-8)
#define LOG_MU2 (-10.99997045f)
#define LOG_NU2 (-10.99997045f)
#define NEG_BIG (-3.0e38f)

__device__ __forceinline__ float ex2f(float x) {
    float r; asm("ex2.approx.f32 %0, %1;" : "=f"(r) : "f"(x)); return r;
}
__device__ __forceinline__ float lg2f(float x) {
    float r; asm("lg2.approx.f32 %0, %1;" : "=f"(r) : "f"(x)); return r;
}

// ---------------- static device scratch -----------------------------------
__device__ float g_us2[NB * P];
__device__ float g_vs2[NB * P];
__device__ float g_xx[NB * P];
__device__ float g_yy[NB * P];
__device__ float g_pm2[NB * RCHUNKS * P];
__device__ float g_ps2[NB * RCHUNKS * P];
__device__ float g_cp[NB * 1024];
__device__ unsigned g_ticket[NB * JBLKS];

// ---------------- init -------------------------------------------------------
__global__ void init_kernel() {
    int t = blockIdx.x * 256 + threadIdx.x;
    if (t < NB * P) g_vs2[t] = 0.0f;
    if (t < NB * JBLKS) g_ticket[t] = 0u;
}

// ---------------- squared norms ----------------------------------------------
__global__ __launch_bounds__(256) void norms_kernel(const float* __restrict__ x,
                                                    const float* __restrict__ y) {
    const int r = blockIdx.x * 256 + threadIdx.x;
    const float4* xr = (const float4*)(x + (size_t)r * D);
    const float4* yr = (const float4*)(y + (size_t)r * D);
    float ax = 0.0f, ay = 0.0f;
#pragma unroll
    for (int t = 0; t < D / 4; t++) {
        float4 a = xr[t], b = yr[t];
        ax = fmaf(a.x, a.x, ax); ax = fmaf(a.y, a.y, ax);
        ax = fmaf(a.z, a.z, ax); ax = fmaf(a.w, a.w, ax);
        ay = fmaf(b.x, b.x, ay); ay = fmaf(b.y, b.y, ay);
        ay = fmaf(b.z, b.z, ay); ay = fmaf(b.w, b.w, ay);
    }
    g_xx[r] = ax;
    g_yy[r] = ay;
}

// ---------------- C = xx_i + yy_j - 2*x.y ---------------------------------------
__global__ __launch_bounds__(256) void c_kernel(const float* __restrict__ x,
                                                const float* __restrict__ y,
                                                float* __restrict__ C) {
    __shared__ float Xs[64][68];
    __shared__ float Ys[64][68];
    const int tx = threadIdx.x, ty = threadIdx.y;
    const int tid = ty * 16 + tx;
    const int n  = blockIdx.z;
    const int i0 = blockIdx.y * 64;
    const int j0 = blockIdx.x * 64;

    {
        const int r  = tid >> 2;
        const int c4 = tid & 3;
        const float* xg = x + ((size_t)n * P + i0 + r) * D;
        const float* yg = y + ((size_t)n * P + j0 + r) * D;
#pragma unroll
        for (int q = 0; q < 4; q++) {
            int col = c4 * 16 + q * 4;
            *(float4*)&Xs[r][col] = *(const float4*)(xg + col);
            *(float4*)&Ys[r][col] = *(const float4*)(yg + col);
        }
    }
    __syncthreads();

    float acc[4][4];
#pragma unroll
    for (int a = 0; a < 4; a++)
#pragma unroll
        for (int b = 0; b < 4; b++) acc[a][b] = 0.0f;

#pragma unroll
    for (int k = 0; k < D; k += 4) {
        float4 xa[4], yb[4];
#pragma unroll
        for (int a = 0; a < 4; a++) xa[a] = *(float4*)&Xs[ty * 4 + a][k];
#pragma unroll
        for (int b = 0; b < 4; b++) yb[b] = *(float4*)&Ys[tx * 4 + b][k];
#pragma unroll
        for (int a = 0; a < 4; a++)
#pragma unroll
            for (int b = 0; b < 4; b++) {
                acc[a][b] = fmaf(xa[a].x, yb[b].x, acc[a][b]);
                acc[a][b] = fmaf(xa[a].y, yb[b].y, acc[a][b]);
                acc[a][b] = fmaf(xa[a].z, yb[b].z, acc[a][b]);
                acc[a][b] = fmaf(xa[a].w, yb[b].w, acc[a][b]);
            }
    }

    float yyv[4];
#pragma unroll
    for (int b = 0; b < 4; b++) yyv[b] = g_yy[(n << 11) + j0 + tx * 4 + b];

    float* Cb = C + (size_t)n * P * P;
#pragma unroll
    for (int a = 0; a < 4; a++) {
        float xxv = g_xx[(n << 11) + i0 + ty * 4 + a];
        float4 o;
        o.x = fmaf(-2.0f, acc[a][0], xxv + yyv[0]);
        o.y = fmaf(-2.0f, acc[a][1], xxv + yyv[1]);
        o.z = fmaf(-2.0f, acc[a][2], xxv + yyv[2]);
        o.w = fmaf(-2.0f, acc[a][3], xxv + yyv[3]);
        *(float4*)&Cb[(size_t)(i0 + ty * 4 + a) * P + j0 + tx * 4] = o;
    }
}

// ---------------- LSE helper (slow/safe path) -------------------------------------
__device__ __forceinline__ void lse_group(float4 c, float vx, float vy, float vz, float vw,
                                          float& m, float& s) {
    float b0 = fmaf(c.x, -K2E, vx);
    float b1 = fmaf(c.y, -K2E, vy);
    float b2 = fmaf(c.z, -K2E, vz);
    float b3 = fmaf(c.w, -K2E, vw);
    float cm = fmaxf(fmaxf(b0, b1), fmaxf(b2, b3));
    float mn = fmaxf(m, cm);
    s = fmaf(s, ex2f(m - mn),
             ex2f(b0 - mn) + ex2f(b1 - mn) + ex2f(b2 - mn) + ex2f(b3 - mn));
    m = mn;
}

// ---------------- K1: row pass ------------------------------------------------------
// grid = NB*P/8 blocks, 8 warps/block, 1 row per warp.
__global__ __launch_bounds__(256) void row_k1(const float* __restrict__ C, int fast) {
    __shared__ float vs[P];
    const int lane = threadIdx.x & 31;
    const int warp = threadIdx.x >> 5;
    const int row  = blockIdx.x * 8 + warp;      // 0..8191
    const int n    = row >> 11;

    {
        const float4* src = (const float4*)(g_vs2 + (n << 11));
        float4* dst = (float4*)vs;
#pragma unroll
        for (int t = threadIdx.x; t < P / 4; t += 256) dst[t] = src[t];
    }
    __syncthreads();

    const float4* Crow = (const float4*)(C + (size_t)row * P);
    const float4* V4   = (const float4*)vs;

    if (fast) {
        // ref = lse_prev = LOG_MU2 - us2_prev  ->  us2_new = us2_prev - log2(s)
        const float uprev = g_us2[row];
        const float ref   = LOG_MU2 - uprev;
        float s0 = 0.0f, s1 = 0.0f, s2 = 0.0f, s3 = 0.0f;
#pragma unroll
        for (int k = 0; k < 16; k++) {
            const int t = lane + k * 32;
            float4 c  = Crow[t];
            float4 vv = V4[t];
            s0 += ex2f(fmaf(c.x, -K2E, vv.x) - ref);
            s1 += ex2f(fmaf(c.y, -K2E, vv.y) - ref);
            s2 += ex2f(fmaf(c.z, -K2E, vv.z) - ref);
            s3 += ex2f(fmaf(c.w, -K2E, vv.w) - ref);
        }
        float s = (s0 + s1) + (s2 + s3);
#pragma unroll
        for (int o = 16; o; o >>= 1)
            s += __shfl_xor_sync(0xffffffffu, s, o);
        if (lane == 0) g_us2[row] = uprev - lg2f(s);
    } else {
        float m0 = NEG_BIG, ss0 = 0.0f, m1 = NEG_BIG, ss1 = 0.0f;
#pragma unroll
        for (int k = 0; k < 8; k++) {
            const int t0 = lane + k * 64;
            const int t1 = t0 + 32;
            float4 c0 = Crow[t0];
            float4 c1 = Crow[t1];
            float4 v0 = V4[t0];
            float4 v1 = V4[t1];
            lse_group(c0, v0.x, v0.y, v0.z, v0.w, m0, ss0);
            lse_group(c1, v1.x, v1.y, v1.z, v1.w, m1, ss1);
        }
        float m = fmaxf(m0, m1);
        float s = ss0 * ex2f(m0 - m) + ss1 * ex2f(m1 - m);
#pragma unroll
        for (int o = 16; o; o >>= 1) {
            float mo = __shfl_xor_sync(0xffffffffu, m, o);
            float so = __shfl_xor_sync(0xffffffffu, s, o);
            float mn = fmaxf(m, mo);
            s = s * ex2f(m - mn) + so * ex2f(mo - mn);
            m = mn;
        }
        if (lane == 0) g_us2[row] = LOG_MU2 - (m + lg2f(s));
    }
}

// ---------------- K2: column pass + fused combine ------------------------------------
// grid = NB*RCHUNKS*JBLKS = 512 blocks, 256 thr, 2 columns/thread (float2 loads).
__global__ __launch_bounds__(256) void col_k2(const float* __restrict__ C, int fast) {
    __shared__ float us[CHUNK_ROWS];
    __shared__ unsigned lastv;
    const int b     = blockIdx.x;
    const int jb    = b & (JBLKS - 1);
    const int chunk = (b >> 2) & (RCHUNKS - 1);
    const int n     = b >> 7;
    const int j0    = (jb << 9) + (threadIdx.x << 1);   // 2 cols per thread
    const int i0    = chunk << 6;

    if (threadIdx.x < CHUNK_ROWS)
        us[threadIdx.x] = g_us2[(n << 11) + i0 + threadIdx.x];
    __syncthreads();

    const float2* Cc = (const float2*)(C + (size_t)n * P * P + (size_t)i0 * P) + (j0 >> 1);
    const size_t po = ((size_t)n * RCHUNKS + chunk) * P + j0;

    float ref0 = 0.0f, ref1 = 0.0f;
    if (fast) {
        ref0 = LOG_NU2 - g_vs2[(n << 11) + j0];
        ref1 = LOG_NU2 - g_vs2[(n << 11) + j0 + 1];
        float a0 = 0.0f, a1 = 0.0f, b0 = 0.0f, b1 = 0.0f;
#pragma unroll
        for (int i = 0; i < CHUNK_ROWS; i += 4) {
            float2 r0 = Cc[(size_t)(i + 0) * (P / 2)];
            float2 r1 = Cc[(size_t)(i + 1) * (P / 2)];
            float2 r2 = Cc[(size_t)(i + 2) * (P / 2)];
            float2 r3 = Cc[(size_t)(i + 3) * (P / 2)];
            a0 += ex2f(fmaf(r0.x, -K2E, us[i + 0]) - ref0);
            a1 += ex2f(fmaf(r0.y, -K2E, us[i + 0]) - ref1);
            b0 += ex2f(fmaf(r1.x, -K2E, us[i + 1]) - ref0);
            b1 += ex2f(fmaf(r1.y, -K2E, us[i + 1]) - ref1);
            a0 += ex2f(fmaf(r2.x, -K2E, us[i + 2]) - ref0);
            a1 += ex2f(fmaf(r2.y, -K2E, us[i + 2]) - ref1);
            b0 += ex2f(fmaf(r3.x, -K2E, us[i + 3]) - ref0);
            b1 += ex2f(fmaf(r3.y, -K2E, us[i + 3]) - ref1);
        }
        g_ps2[po]     = a0 + b0;
        g_ps2[po + 1] = a1 + b1;
    } else {
        float m0 = NEG_BIG, s0 = 0.0f, m1 = NEG_BIG, s1 = 0.0f;
#pragma unroll
        for (int i = 0; i < CHUNK_ROWS; i += 4) {
            float2 r0 = Cc[(size_t)(i + 0) * (P / 2)];
            float2 r1 = Cc[(size_t)(i + 1) * (P / 2)];
            float2 r2 = Cc[(size_t)(i + 2) * (P / 2)];
            float2 r3 = Cc[(size_t)(i + 3) * (P / 2)];
            float4 c0 = {r0.x, r1.x, r2.x, r3.x};
            float4 c1 = {r0.y, r1.y, r2.y, r3.y};
            lse_group(c0, us[i], us[i + 1], us[i + 2], us[i + 3], m0, s0);
            lse_group(c1, us[i], us[i + 1], us[i + 2], us[i + 3], m1, s1);
        }
        g_pm2[po] = m0;     g_ps2[po] = s0;
        g_pm2[po + 1] = m1; g_ps2[po + 1] = s1;
    }

    // ticket: last chunk-block for (n, jb) combines all RCHUNKS partials
    __threadfence();
    if (threadIdx.x == 0) lastv = atomicAdd(&g_ticket[n * JBLKS + jb], 1u);
    __syncthreads();
    if (lastv == RCHUNKS - 1) {
        __threadfence();
        if (fast) {
            float ss0 = 0.0f, ss1 = 0.0f;
#pragma unroll
            for (int c = 0; c < RCHUNKS; c++) {
                size_t idx = ((size_t)n * RCHUNKS + c) * P + j0;
                ss0 += __ldcg(&g_ps2[idx]);
                ss1 += __ldcg(&g_ps2[idx + 1]);
            }
            // vs_new = LOG_NU2 - (ref + log2(ss)) = vs_prev - log2(ss)
            g_vs2[(n << 11) + j0]     = (LOG_NU2 - ref0) - lg2f(ss0);
            g_vs2[(n << 11) + j0 + 1] = (LOG_NU2 - ref1) - lg2f(ss1);
        } else {
#pragma unroll
            for (int cc = 0; cc < 2; cc++) {
                const int j = j0 + cc;
                float mm = NEG_BIG;
#pragma unroll
                for (int c = 0; c < RCHUNKS; c++)
                    mm = fmaxf(mm, __ldcg(&g_pm2[((size_t)n * RCHUNKS + c) * P + j]));
                float ss = 0.0f;
#pragma unroll
                for (int c = 0; c < RCHUNKS; c++) {
                    size_t idx = ((size_t)n * RCHUNKS + c) * P + j;
                    ss += __ldcg(&g_ps2[idx]) * ex2f(__ldcg(&g_pm2[idx]) - mm);
                }
                g_vs2[(n << 11) + j] = LOG_NU2 - (mm + lg2f(ss));
            }
        }
        if (threadIdx.x == 0) g_ticket[n * JBLKS + jb] = 0u;
    }
}

// ---------------- pi + cost partials ----------------------------------------------
__global__ __launch_bounds__(256) void pi_cost(const float* __restrict__ C,
                                               float* __restrict__ pi) {
    __shared__ float red[256];
    const int b = blockIdx.x;
    const int n = b >> 10;
    const float4* C4 = (const float4*)C;
    float4* P4 = (float4*)pi;
    const float4* V4 = (const float4*)(g_vs2 + (n << 11));
    const size_t base = (size_t)b * 1024;

    float acc = 0.0f;
#pragma unroll
    for (int p = 0; p < 4; p++) {
        size_t f4 = base + (size_t)p * 256 + threadIdx.x;
        float4 c = C4[f4];
        int ig = (int)(f4 >> 9);
        float u = g_us2[ig];
        float4 vv = V4[f4 & (P / 4 - 1)];
        float4 pv;
        pv.x = ex2f(fmaf(c.x, -K2E, u + vv.x));
        pv.y = ex2f(fmaf(c.y, -K2E, u + vv.y));
        pv.z = ex2f(fmaf(c.z, -K2E, u + vv.z));
        pv.w = ex2f(fmaf(c.w, -K2E, u + vv.w));
        P4[f4] = pv;
        acc += pv.x * c.x + pv.y * c.y + pv.z * c.z + pv.w * c.w;
    }
    red[threadIdx.x] = acc;
    __syncthreads();
#pragma unroll
    for (int o = 128; o; o >>= 1) {
        if (threadIdx.x < o) red[threadIdx.x] += red[threadIdx.x + o];
        __syncthreads();
    }
    if (threadIdx.x == 0) g_cp[b] = red[0];
}

__global__ __launch_bounds__(256) void cost_combine(float* __restrict__ cost) {
    __shared__ float red[256];
    const int n = blockIdx.x;
    float a = 0.0f;
#pragma unroll
    for (int q = 0; q < 4; q++)
        a += g_cp[n * 1024 + q * 256 + threadIdx.x];
    red[threadIdx.x] = a;
    __syncthreads();
#pragma unroll
    for (int o = 128; o; o >>= 1) {
        if (threadIdx.x < o) red[threadIdx.x] += red[threadIdx.x + o];
        __syncthreads();
    }
    if (threadIdx.x == 0) cost[n] = red[0];
}

// ---------------- launch --------------------------------------------------------------
extern "C" void kernel_launch(void* const* d_in, const int* in_sizes, int n_in,
                              void* d_out, int out_size) {
    const float* x = (const float*)d_in[0];
    const float* y = (const float*)d_in[1];
    float* out  = (float*)d_out;
    float* cost = out;
    float* pi   = out + NB;
    float* C    = out + NB + (size_t)NB * P * P;

    init_kernel<<<32, 256>>>();
    norms_kernel<<<NB * P / 256, 256>>>(x, y);
    c_kernel<<<dim3(P / 64, P / 64, NB), dim3(16, 16)>>>(x, y, C);

    for (int it = 0; it < ITERS; it++) {
        const int fast = (it >= 2) ? 1 : 0;
        row_k1<<<NB * P / 8, 256>>>(C, fast);
        col_k2<<<NB * RCHUNKS * JBLKS, 256>>>(C, fast);
    }

    pi_cost<<<NB * 1024, 256>>>(C, pi);
    cost_combine<<<NB, 256>>>(cost);
}